// round 2
// baseline (speedup 1.0000x reference)
#include <cuda_runtime.h>
#include <cuda_fp16.h>

#define T_STEPS 1024
#define BATCH   64
#define ICH     512
#define HCH     512
#define G4      2048
#define NLAYER  2
#define NBLK    128

// ---------------- scratch (static device globals; no allocation) ------------
__device__ __align__(16) float  g_xi[134217728];   // [T][B][2048] reused per layer (512MB)
__device__ __align__(16) float  g_hs0[33554432];   // layer0 h sequence [T][B][512] (128MB)
__device__ __align__(16) __half g_hbuf[2][BATCH*HCH];
__device__ __align__(16) __half g_Wi_r[NLAYER*G4*ICH];   // reordered fp16 input weights
__device__ __align__(16) __half g_Wh_r[NLAYER*G4*HCH];   // reordered fp16 recurrent weights
__device__ __align__(16) float  g_bias_r[NLAYER*G4];     // bi+bh, reordered
__device__ unsigned g_bar_cnt;
__device__ volatile unsigned g_bar_gen;

// ---------------- helpers ---------------------------------------------------
__device__ __forceinline__ void mma_f16(float acc[4],
                                        unsigned a0, unsigned a1, unsigned a2, unsigned a3,
                                        unsigned b0, unsigned b1) {
    asm volatile(
        "mma.sync.aligned.m16n8k16.row.col.f32.f16.f16.f32 "
        "{%0,%1,%2,%3},{%4,%5,%6,%7},{%8,%9},{%0,%1,%2,%3};"
        : "+f"(acc[0]), "+f"(acc[1]), "+f"(acc[2]), "+f"(acc[3])
        : "r"(a0), "r"(a1), "r"(a2), "r"(a3), "r"(b0), "r"(b1));
}

__device__ __forceinline__ float sigmf(float x) { return 1.f / (1.f + __expf(-x)); }

__device__ __forceinline__ void grid_barrier(unsigned target) {
    __syncthreads();
    if (threadIdx.x == 0) {
        __threadfence();
        unsigned prev = atomicAdd(&g_bar_cnt, 1u);
        if (prev == NBLK - 1u) {
            g_bar_cnt = 0u;
            __threadfence();
            g_bar_gen = target;
        } else {
            while (g_bar_gen < target) {}
        }
        __threadfence();
    }
    __syncthreads();
}

// ---------------- init: reset barrier state (needed per graph replay) -------
__global__ void k_init() { g_bar_cnt = 0u; g_bar_gen = 0u; }

// ---------------- reorder weights to interleaved-gate fp16 ------------------
// dest row n' = 4*j + s  <->  source row s*512 + j   (s in {f,i,o,g})
__global__ void k_reorder(const float* __restrict__ Wi, const float* __restrict__ bi,
                          const float* __restrict__ Wh, const float* __restrict__ bh) {
    unsigned idx = blockIdx.x * 256u + threadIdx.x;   // over 2*2048*512 = 2097152
    if (idx >= 2097152u) return;
    int k  = idx & 511;
    int np = (idx >> 9) & 2047;
    int l  = idx >> 20;
    int s  = np & 3;
    int j  = np >> 2;
    size_t src = ((size_t)l * G4 + s * 512 + j) * 512 + k;
    g_Wi_r[idx] = __float2half_rn(Wi[src]);
    g_Wh_r[idx] = __float2half_rn(Wh[src]);
    if (k == 0)
        g_bias_r[l * G4 + np] = bi[l * G4 + s * 512 + j] + bh[l * G4 + s * 512 + j];
}

// ---------------- big input-projection GEMM ---------------------------------
// C[65536, 2048] = A[65536, 512] (fp32->fp16) x Wr[2048, 512]^T + bias
// BM=128 BN=64 BK=32, 256 threads (8 warps, 4x2), warp tile 32x32, mma m16n8k16
__global__ __launch_bounds__(256) void k_gemm(const float* __restrict__ Ain, int layer) {
    __shared__ unsigned As[128][20];   // word w = halves (2w,2w+1); pad->conflict-free
    __shared__ unsigned Bs[64][20];

    const float*  A    = Ain ? Ain : g_hs0;
    const __half* W    = g_Wi_r + (size_t)layer * G4 * ICH;
    const float*  bias = g_bias_r + layer * G4;
    float*        C    = g_xi;

    int n0 = blockIdx.x * 64, m0 = blockIdx.y * 128;
    int tid = threadIdx.x, lane = tid & 31, warp = tid >> 5;
    int q = lane & 3, gr = lane >> 2;
    int wm = warp & 3, wn = warp >> 2;

    float acc[2][4][4];
#pragma unroll
    for (int mi = 0; mi < 2; mi++)
#pragma unroll
        for (int ni = 0; ni < 4; ni++)
#pragma unroll
            for (int e = 0; e < 4; e++) acc[mi][ni][e] = 0.f;

    for (int k0 = 0; k0 < 512; k0 += 32) {
        // A tile: 128x32 floats -> fp16 smem
#pragma unroll
        for (int i = 0; i < 4; i++) {
            int f4 = tid + i * 256;          // 0..1023
            int r = f4 >> 3, c4 = f4 & 7;
            float4 v = *(const float4*)&A[(size_t)(m0 + r) * 512 + k0 + c4 * 4];
            __half2 h01 = __floats2half2_rn(v.x, v.y);
            __half2 h23 = __floats2half2_rn(v.z, v.w);
            As[r][c4 * 2]     = *(unsigned*)&h01;
            As[r][c4 * 2 + 1] = *(unsigned*)&h23;
        }
        // B tile: 64x32 halves
#pragma unroll
        for (int i = 0; i < 2; i++) {
            int e = tid + i * 256;           // 0..511 uint2
            int r = e >> 3, u = e & 7;
            uint2 v = *(const uint2*)(W + (size_t)(n0 + r) * 512 + k0 + u * 4);
            Bs[r][u * 2] = v.x;
            Bs[r][u * 2 + 1] = v.y;
        }
        __syncthreads();

#pragma unroll
        for (int kt = 0; kt < 2; kt++) {
            unsigned a[2][4];
#pragma unroll
            for (int mi = 0; mi < 2; mi++) {
                int r0 = wm * 32 + mi * 16 + gr;
                a[mi][0] = As[r0][kt * 8 + q];
                a[mi][1] = As[r0 + 8][kt * 8 + q];
                a[mi][2] = As[r0][kt * 8 + q + 4];
                a[mi][3] = As[r0 + 8][kt * 8 + q + 4];
            }
#pragma unroll
            for (int ni = 0; ni < 4; ni++) {
                int br = wn * 32 + ni * 8 + gr;
                unsigned b0 = Bs[br][kt * 8 + q];
                unsigned b1 = Bs[br][kt * 8 + q + 4];
#pragma unroll
                for (int mi = 0; mi < 2; mi++)
                    mma_f16(acc[mi][ni], a[mi][0], a[mi][1], a[mi][2], a[mi][3], b0, b1);
            }
        }
        __syncthreads();
    }

    // epilogue: + (bi+bh), fp32 store
#pragma unroll
    for (int mi = 0; mi < 2; mi++)
#pragma unroll
        for (int ni = 0; ni < 4; ni++) {
            int row  = m0 + wm * 32 + mi * 16 + gr;
            int ncol = n0 + wn * 32 + ni * 8 + 2 * q;
            float2 bb = *(const float2*)&bias[ncol];
            float2 o;
            o.x = acc[mi][ni][0] + bb.x; o.y = acc[mi][ni][1] + bb.y;
            *(float2*)&C[(size_t)row * G4 + ncol] = o;
            o.x = acc[mi][ni][2] + bb.x; o.y = acc[mi][ni][3] + bb.y;
            *(float2*)&C[(size_t)(row + 8) * G4 + ncol] = o;
        }
}

// ---------------- persistent recurrent kernel -------------------------------
// 128 blocks x 128 threads. Block b owns gate' rows [16b,16b+16) <-> h cols [4b,4b+4).
// Per step: gates[64x16] = xi_t + h[64x512] @ WhSlice^T via fp16 mma; elementwise;
// h double-buffered fp16 in gmem (L2), read with __ldcg; grid barrier per step.
__global__ __launch_bounds__(128, 1) void k_lstm(int layer,
                                                 const float* __restrict__ h0l,
                                                 const float* __restrict__ c0l,
                                                 float* __restrict__ ybase,
                                                 float* __restrict__ hT,
                                                 float* __restrict__ cT) {
    __shared__ uint2 sWh[16][132];   // [gate' row local][uint2 over K=512 halves], padded
    __shared__ float sG[64][20];     // gate accumulators [batch][local n'], padded

    int b = blockIdx.x, tid = threadIdx.x;
    int lane = tid & 31, warp = tid >> 5;
    int q = lane & 3, gr = lane >> 2;
    float* hseq = (layer == 0) ? g_hs0 : ybase;

    // load this block's Wh slice (16 x 512 fp16) into smem
    const uint2* WhU = (const uint2*)(g_Wh_r + (size_t)layer * G4 * HCH);
#pragma unroll
    for (int i = 0; i < 16; i++) {
        int w = tid + i * 128;        // 0..2047
        int r = w >> 7, c = w & 127;
        sWh[r][c] = WhU[(size_t)(16 * b + r) * 128 + c];
    }

    // init c (registers) and h buffer slice
    float creg[2];
#pragma unroll
    for (int s = 0; s < 2; s++) {
        int idx = tid + s * 128;
        int batch = idx >> 2, jl = idx & 3, col = 4 * b + jl;
        creg[s] = c0l[batch * HCH + col];
        g_hbuf[0][batch * HCH + col] = __float2half_rn(h0l[batch * HCH + col]);
    }
    __threadfence();
    unsigned gen = 0;
    grid_barrier(++gen);

    int rb = 16 * warp + gr;   // batch row for A fragments

    for (int t = 0; t < T_STEPS; t++) {
        const uint2* hb = (const uint2*)g_hbuf[t & 1];
        float acc[2][4];
#pragma unroll
        for (int nt = 0; nt < 2; nt++)
#pragma unroll
            for (int e = 0; e < 4; e++) acc[nt][e] = 0.f;

        // K-permuted fragments: uint2 covers phys k = 16*kt + 4q..4q+3 for BOTH A and B,
        // so each 32B L2 sector is fully consumed.
#pragma unroll 4
        for (int kt = 0; kt < 32; kt++) {
            int wi = kt * 4 + q;
            uint2 va = __ldcg(&hb[rb * 128 + wi]);
            uint2 vb = __ldcg(&hb[(rb + 8) * 128 + wi]);
#pragma unroll
            for (int nt = 0; nt < 2; nt++) {
                uint2 wv = sWh[nt * 8 + gr][wi];
                mma_f16(acc[nt], va.x, vb.x, va.y, vb.y, wv.x, wv.y);
            }
        }

        // accumulators -> smem (natural [batch][gate'] layout)
#pragma unroll
        for (int nt = 0; nt < 2; nt++) {
            int nc = nt * 8 + 2 * q;
            *(float2*)&sG[16 * warp + gr][nc]     = make_float2(acc[nt][0], acc[nt][1]);
            *(float2*)&sG[16 * warp + gr + 8][nc] = make_float2(acc[nt][2], acc[nt][3]);
        }
        __syncthreads();

        // elementwise LSTM cell update
        const float* xit = g_xi + (size_t)t * BATCH * G4;
        __half* hn = g_hbuf[(t + 1) & 1];
#pragma unroll
        for (int s = 0; s < 2; s++) {
            int idx = tid + s * 128;
            int batch = idx >> 2, jl = idx & 3, col = 4 * b + jl;
            float4 xv = *(const float4*)&xit[batch * G4 + 16 * b + 4 * jl];
            float gf = sG[batch][4 * jl + 0] + xv.x;
            float gi = sG[batch][4 * jl + 1] + xv.y;
            float go = sG[batch][4 * jl + 2] + xv.z;
            float gg = sG[batch][4 * jl + 3] + xv.w;
            float f  = sigmf(gf);
            float ii = sigmf(gi);
            float o  = sigmf(go);
            float g  = tanhf(gg);
            float c  = creg[s] * f + ii * g;
            creg[s]  = c;
            float h  = o * tanhf(c);
            hn[batch * HCH + col] = __float2half_rn(h);
            hseq[(size_t)t * BATCH * HCH + batch * HCH + col] = h;
            if (t == T_STEPS - 1) {
                hT[batch * HCH + col] = h;
                cT[batch * HCH + col] = c;
            }
        }
        __threadfence();
        grid_barrier(++gen);
    }
}

// ---------------- launch ----------------------------------------------------
extern "C" void kernel_launch(void* const* d_in, const int* in_sizes, int n_in,
                              void* d_out, int out_size) {
    const float* x  = (const float*)d_in[0];
    const float* Wi = (const float*)d_in[1];
    const float* bi = (const float*)d_in[2];
    const float* Wh = (const float*)d_in[3];
    const float* bh = (const float*)d_in[4];
    const float* h0 = (const float*)d_in[5];
    const float* c0 = (const float*)d_in[6];

    float* out = (float*)d_out;
    float* y   = out;                                   // [T,B,HC]
    float* hsO = out + (size_t)T_STEPS * BATCH * HCH;   // [L,B,HC]
    float* csO = hsO + (size_t)NLAYER * BATCH * HCH;    // [L,B,HC]

    k_reorder<<<8192, 256>>>(Wi, bi, Wh, bh);

    // layer 0
    k_gemm<<<dim3(32, 512), 256>>>(x, 0);
    k_init<<<1, 1>>>();
    k_lstm<<<NBLK, 128>>>(0, h0, c0, y, hsO, csO);

    // layer 1
    k_gemm<<<dim3(32, 512), 256>>>(nullptr, 1);
    k_init<<<1, 1>>>();
    k_lstm<<<NBLK, 128>>>(1, h0 + BATCH * HCH, c0 + BATCH * HCH, y,
                          hsO + BATCH * HCH, csO + BATCH * HCH);

    (void)in_sizes; (void)n_in; (void)out_size;
}